// round 17
// baseline (speedup 1.0000x reference)
#include <cuda_runtime.h>
#include <cuda_fp16.h>
#include <cstdint>

// GRUConv3d R17: R16 + fp16 scratch for the conv->scan interface.
// hb/z/s stored as __half (conv writes halved, scan reads halved); scan
// computes in fp32 and writes contrib to a separate fp32 buffer g_ct.
// Conv mainloop unchanged (mma.sync m16n8k16 fp16, fp32 accumulate).

#define NDIR 8
#define B_   2
#define C_   32
#define SPAT 32768
#define NT   (NDIR * B_ * C_ * SPAT)

// scratch, layout [n][b][sp][c] (c fastest)
__device__ __align__(16) __half g_hbh[NT];   // conv-h out (fp16)
__device__ __align__(16) __half g_zh [NT];   // sigmoid z  (fp16)
__device__ __align__(16) __half g_sh [NT];   // sigmoid s  (fp16)
__device__ float g_ct[NT];                   // contrib = O*s (fp32)
__device__ __align__(16) __half g_xh[B_ * C_ * SPAT];       // x in fp16
// weight frags: [g 24][cc2 2][td 3][t9 9][f 2][lane 32][r 4] (half2 words)
__device__ __align__(16) unsigned g_wt[24 * 2 * 3 * 9 * 256];

__device__ __forceinline__ unsigned pack_h2(__half lo, __half hi) {
    return (unsigned)__half_as_ushort(lo) | ((unsigned)__half_as_ushort(hi) << 16);
}

// ---------------------------------------------------------------------------
// Prep kernels
// ---------------------------------------------------------------------------
__global__ void prep_x(const float* __restrict__ x)
{
    int i = blockIdx.x * 256 + threadIdx.x;
    if (i < B_ * C_ * SPAT) g_xh[i] = __float2half_rn(x[i]);
}

__global__ void prep_w(const float* __restrict__ Wh,
                       const float* __restrict__ Wz,
                       const float* __restrict__ Ws)
{
    int idx = blockIdx.x * 256 + threadIdx.x;
    if (idx >= 24 * 2 * 3 * 9 * 256) return;
    int r    = idx & 3;
    int lane = (idx >> 2) & 31;
    int f    = (idx >> 7) & 1;
    int t9   = (idx >> 8) % 9;
    int q    = (idx >> 8) / 9;
    int td  = q % 3; q /= 3;
    int cc2 = q & 1; int g = q >> 1;

    int qrow = lane >> 2, qcol = lane & 3;
    int co = f * 16 + qrow + (r & 1) * 8;
    int k0 = 2 * qcol + (r >> 1) * 8;
    int th = t9 / 3, tw = t9 % 3;
    int ci0 = cc2 * 16 + k0;
    int n = g / 3, gate = g % 3;
    const float* W = (gate == 0) ? Wh : (gate == 1) ? Wz : Ws;
    size_t wb = ((size_t)n * 32 + co) * 32;
    int tap = td * 9 + th * 3 + tw;
    __half lo = __float2half_rn(W[(wb + ci0    ) * 27 + tap]);
    __half hi = __float2half_rn(W[(wb + ci0 + 1) * 27 + tap]);
    g_wt[idx] = pack_h2(lo, hi);
}

// ---------------------------------------------------------------------------
// Conv (mainloop identical to R16); epilogue -> smem transpose -> fp16 STG.
// ---------------------------------------------------------------------------
#define MMA_F16(d, a, b0, b1)                                                \
    asm volatile("mma.sync.aligned.m16n8k16.row.col.f32.f16.f16.f32 "        \
                 "{%0,%1,%2,%3}, {%4,%5,%6,%7}, {%8,%9}, {%0,%1,%2,%3};"     \
                 : "+f"(d[0]), "+f"(d[1]), "+f"(d[2]), "+f"(d[3])            \
                 : "r"(a.x), "r"(a.y), "r"(a.z), "r"(a.w),                   \
                   "r"(b0), "r"(b1))

#define XS_STRIDE 1032
#define WF_OFF    8256
#define SM_WORDS  (WF_OFF + 4608)
#define SM_BYTES  (SM_WORDS * 4)       // 51456 B (>= 256*36*4 = 36864 for Ts)

extern "C" __global__ void __launch_bounds__(256, 2)
conv_mma2(const float* __restrict__ bh, const float* __restrict__ bz,
          const float* __restrict__ bs)
{
    extern __shared__ unsigned sm[];
    unsigned* Xs = sm;                 // [cp 8][(td*10+hh)*34+ww] half2 words
    unsigned* WF = sm + WF_OFF;        // [g2][t9][f][lane][4]

    const int ng  = blockIdx.x >> 8;   // 0..11
    const int nt  = blockIdx.x & 255;
    const int b   = nt >> 7;
    const int d   = (nt >> 2) & 31;
    const int h0v = (nt & 3) * 8;
    const int g0  = ng * 2;

    const int tid  = threadIdx.x;
    const int wid  = tid >> 5;
    const int lane = tid & 31;
    const int qrow = lane >> 2;
    const int qcol = lane & 3;

    const __half* xb = g_xh + (size_t)b * (C_ * SPAT);

    float acc[2][2][4][4];
    #pragma unroll
    for (int gi = 0; gi < 2; gi++)
        #pragma unroll
        for (int f = 0; f < 2; f++)
            #pragma unroll
            for (int j = 0; j < 4; j++)
                #pragma unroll
                for (int r = 0; r < 4; r++) acc[gi][f][j][r] = 0.f;

    for (int cc2 = 0; cc2 < 2; cc2++) {        // cin chunks of 16
        __syncthreads();
        for (int idx = tid; idx < 8160; idx += 256) {
            int cp = idx / 1020;
            int r  = idx % 1020;
            int ww = r % 34;
            int t  = r / 34;
            int hh = t % 10;
            int td = t / 10;
            int gd = d - 1 + td;
            int gh = h0v - 1 + hh;
            int gw = ww - 1;
            unsigned v = 0u;
            if ((unsigned)gd < 32u && (unsigned)gh < 32u && (unsigned)gw < 32u) {
                size_t off = (size_t)(cc2 * 16 + cp * 2) * SPAT
                           + gd * 1024 + gh * 32 + gw;
                v = pack_h2(xb[off], xb[off + SPAT]);
            }
            Xs[cp * XS_STRIDE + r] = v;
        }

        for (int td = 0; td < 3; td++) {
            __syncthreads();
            {
                const uint4* w0 = (const uint4*)(g_wt +
                    ((size_t)((g0    ) * 2 + cc2) * 3 + td) * 2304);
                const uint4* w1 = (const uint4*)(g_wt +
                    ((size_t)((g0 + 1) * 2 + cc2) * 3 + td) * 2304);
                uint4* wf0 = (uint4*)WF;
                uint4* wf1 = (uint4*)(WF + 2304);
                for (int i4 = tid; i4 < 576; i4 += 256) {
                    wf0[i4] = w0[i4];
                    wf1[i4] = w1[i4];
                }
            }
            __syncthreads();

            #pragma unroll
            for (int t9 = 0; t9 < 9; t9++) {
                const int th = t9 / 3, tw = t9 % 3;
                const uint4 a00 = *(const uint4*)(WF +        (t9 * 2    ) * 128 + lane * 4);
                const uint4 a01 = *(const uint4*)(WF +        (t9 * 2 + 1) * 128 + lane * 4);
                const uint4 a10 = *(const uint4*)(WF + 2304 + (t9 * 2    ) * 128 + lane * 4);
                const uint4 a11 = *(const uint4*)(WF + 2304 + (t9 * 2 + 1) * 128 + lane * 4);
                const int xoff = (td * 10 + wid + th) * 34 + tw + qrow;
                #pragma unroll
                for (int j = 0; j < 4; j++) {
                    unsigned b0 = Xs[ qcol      * XS_STRIDE + xoff + 8 * j];
                    unsigned b1 = Xs[(qcol + 4) * XS_STRIDE + xoff + 8 * j];
                    MMA_F16(acc[0][0][j], a00, b0, b1);
                    MMA_F16(acc[0][1][j], a01, b0, b1);
                    MMA_F16(acc[1][0][j], a10, b0, b1);
                    MMA_F16(acc[1][1][j], a11, b0, b1);
                }
            }
        }
    }

    // ---- epilogue: bias/sigmoid -> smem [sp 256][c pad36] -> fp16 STG ----
    float* Ts = (float*)sm;            // 256*36 floats = 36864 B
    #pragma unroll
    for (int gi = 0; gi < 2; gi++) {
        const int g = g0 + gi, gate = g % 3, n = g / 3;
        const float* bptr = (gate == 0) ? bh : (gate == 1) ? bz : bs;
        __half* og = (gate == 0) ? g_hbh : (gate == 1) ? g_zh : g_sh;
        __syncthreads();               // Xs/WF (and prev Ts reads) done
        #pragma unroll
        for (int f = 0; f < 2; f++) {
            #pragma unroll
            for (int part = 0; part < 2; part++) {
                int   co   = f * 16 + qrow + part * 8;
                float bias = bptr[n * 32 + co];
                #pragma unroll
                for (int j = 0; j < 4; j++) {
                    #pragma unroll
                    for (int wp = 0; wp < 2; wp++) {
                        float v = acc[gi][f][j][2 * part + wp] + bias;
                        if (gate > 0) v = 1.f / (1.f + __expf(-v));
                        int w = 8 * j + 2 * qcol + wp;
                        Ts[(wid * 32 + w) * 36 + co] = v;
                    }
                }
            }
        }
        __syncthreads();
        size_t obase = ((size_t)(n * 2 + b) << 20)
                     + (size_t)(d * 1024 + h0v * 32) * 32;
        #pragma unroll
        for (int e = 0; e < 8; e++) {
            int o = e * 1024 + tid * 4;
            int sp_loc = o >> 5, c = o & 31;
            float4 v4 = *(const float4*)(Ts + sp_loc * 36 + c);
            unsigned lo = pack_h2(__float2half_rn(v4.x), __float2half_rn(v4.y));
            unsigned hi = pack_h2(__float2half_rn(v4.z), __float2half_rn(v4.w));
            *(uint2*)(og + obase + o) = make_uint2(lo, hi);
        }
    }
}

// ---------------------------------------------------------------------------
// Scan: one WARP per diagonal chain, lane = channel. fp16 in, fp32 compute,
// fp32 contrib out to g_ct. 16 (n,b) x 2977 chains = 5954 blocks x 8 warps.
// ---------------------------------------------------------------------------
__global__ void __launch_bounds__(256)
scan_kernel(const float* __restrict__ h0)
{
    const int gw   = blockIdx.x * 8 + (threadIdx.x >> 5);
    const int lane = threadIdx.x & 31;
    const int nb   = gw / 2977;
    const int cid  = gw % 2977;
    const int n = nb >> 1;

    const int di = (n & 4) ? 1 : -1;
    const int dj = (n & 2) ? 1 : -1;
    const int dk = (n & 1) ? 1 : -1;
    const int si = (di == 1) ? 0 : 31;
    const int sj = (dj == 1) ? 0 : 31;
    const int sk = (dk == 1) ? 0 : 31;

    int i0, j0, k0;
    if (cid < 1024) {                       // face i == si
        i0 = si; j0 = cid >> 5; k0 = cid & 31;
    } else if (cid < 2016) {                // face j == sj, i != si
        int q = cid - 1024;
        j0 = sj;
        int ii = q >> 5;
        i0 = (di == 1) ? ii + 1 : ii;
        k0 = q & 31;
    } else {                                // face k == sk, i != si, j != sj
        int q = cid - 2016;
        k0 = sk;
        int ii = q / 31;
        int jj = q % 31;
        i0 = (di == 1) ? ii + 1 : ii;
        j0 = (dj == 1) ? jj + 1 : jj;
    }

    int li = (di == 1) ? 32 - i0 : i0 + 1;
    int lj = (dj == 1) ? 32 - j0 : j0 + 1;
    int lk = (dk == 1) ? 32 - k0 : k0 + 1;
    int L  = min(li, min(lj, lk));

    const long long step = (long long)(di * 1024 + dj * 32 + dk) * 32;
    long long p = ((long long)nb << 20)
                + (long long)(i0 * 1024 + j0 * 32 + k0) * 32 + lane;

    float h = h0[n * 32 + lane];
    float zv = __half2float(g_zh[p]);
    float hv = __half2float(g_hbh[p]);
    float sv = __half2float(g_sh[p]);
    for (int s = 0; s < L; s++) {
        long long pn = p + step;
        float zn = 0.f, hn = 0.f, sn = 0.f;
        if (s + 1 < L) {
            zn = __half2float(g_zh[pn]);
            hn = __half2float(g_hbh[pn]);
            sn = __half2float(g_sh[pn]);
        }
        h = fmaf(zv, hv - h, h);            // z*hb + (1-z)*h
        g_ct[p] = h * sv;                   // contrib (fp32)
        zv = zn; hv = hn; sv = sn; p = pn;
    }
}

// ---------------------------------------------------------------------------
// Combine: out[b][c][sp] = sum_n g_ct[n][b][sp][c]; smem transpose.
// ---------------------------------------------------------------------------
__global__ void __launch_bounds__(256)
combine_kernel(float* __restrict__ out)
{
    __shared__ float Ts[256 * 33];
    const int b   = blockIdx.x >> 7;
    const int sp0 = (blockIdx.x & 127) * 256;
    const int tid = threadIdx.x;

    const int c_l  = tid & 31;
    const int sp_h = tid >> 5;          // 0..7
    #pragma unroll
    for (int e = 0; e < 32; e++) {      // 32*8 = 256 sp rows
        int sp_loc = e * 8 + sp_h;
        long long off = (long long)(sp0 + sp_loc) * 32 + c_l + ((long long)b << 20);
        float s = 0.f;
        #pragma unroll
        for (int n = 0; n < 8; n++)
            s += g_ct[((long long)n << 21) + off];
        Ts[sp_loc * 33 + c_l] = s;
    }
    __syncthreads();
    const int sp_l = tid & 31;
    const int c_h  = tid >> 5;          // 0..7
    #pragma unroll
    for (int chunk = 0; chunk < 8; chunk++) {
        int sp_loc = chunk * 32 + sp_l;
        #pragma unroll
        for (int ce = 0; ce < 4; ce++) {
            int c = ce * 8 + c_h;
            out[((size_t)(b * 32 + c) << 15) + sp0 + sp_loc] = Ts[sp_loc * 33 + c];
        }
    }
}

extern "C" void kernel_launch(void* const* d_in, const int* in_sizes, int n_in,
                              void* d_out, int out_size)
{
    const float* x  = (const float*)d_in[0];
    const float* Wh = (const float*)d_in[1];
    const float* bh = (const float*)d_in[2];
    const float* Wz = (const float*)d_in[3];
    const float* bz = (const float*)d_in[4];
    const float* Ws = (const float*)d_in[5];
    const float* bs = (const float*)d_in[6];
    const float* h0 = (const float*)d_in[7];
    float* out = (float*)d_out;

    cudaFuncSetAttribute(conv_mma2, cudaFuncAttributeMaxDynamicSharedMemorySize, SM_BYTES);

    prep_x<<<(B_ * C_ * SPAT + 255) / 256, 256>>>(x);
    prep_w<<<(24 * 2 * 3 * 9 * 256 + 255) / 256, 256>>>(Wh, Wz, Ws);
    conv_mma2<<<12 * 256, 256, SM_BYTES>>>(bh, bz, bs);
    scan_kernel<<<5954, 256>>>(h0);
    combine_kernel<<<256, 256>>>(out);
}